// round 1
// baseline (speedup 1.0000x reference)
#include <cuda_runtime.h>
#include <cstdint>
#include <cstddef>

#define NROWS 131072
#define NSEQ 64
#define TSTEPS 2048
#define FDIM 256
#define HDIM 256

// ---------------- scratch (static device allocations) ----------------
__device__ __align__(16) float g_Wcat[2048 * 256];
__device__ float g_bcat[2048];
__device__ __align__(16) float4 g_Wpack[256 * 256];     // [kk][k] -> {Wi,Wf,Wg,Wo}
__device__ float g_Wp2T[512 * 32];
__device__ __align__(16) float g_f1[(size_t)NROWS * 768];
__device__ __align__(16) float g_opi[(size_t)NROWS * 256];
__device__ __align__(16) float g_xg[(size_t)NROWS * 1024];   // reused: HP = g_xg[0:N*512], HV = g_xg[N*512:]
__device__ __align__(16) float g_hs[(size_t)NROWS * 256];

// ---------------- f32x2 helpers ----------------
__device__ __forceinline__ unsigned long long ffma2(unsigned long long a, unsigned long long b, unsigned long long c) {
    asm("fma.rn.f32x2 %0, %1, %2, %3;" : "=l"(c) : "l"(a), "l"(b), "l"(c));
    return c;
}
__device__ __forceinline__ unsigned long long pack2(float lo, float hi) {
    unsigned long long r;
    asm("mov.b64 %0, {%1, %2};" : "=l"(r) : "f"(lo), "f"(hi));
    return r;
}
__device__ __forceinline__ void unpack2(unsigned long long v, float& a, float& b) {
    asm("mov.b64 {%0, %1}, %2;" : "=f"(a), "=f"(b) : "l"(v));
}

// ---------------- prep: stack weights, pack W_hh, transpose Wp2 ----------------
__global__ void prep_kernel(const float* __restrict__ W_feat, const float* __restrict__ b_feat,
                            const float* __restrict__ W_emb, const float* __restrict__ b_emb,
                            const float* __restrict__ W_ih, const float* __restrict__ W_hh,
                            const float* __restrict__ b_ih, const float* __restrict__ b_hh,
                            const float* __restrict__ Wp2) {
    int i = blockIdx.x * 256 + threadIdx.x;   // up to 524288
    {
        int r = i >> 8;
        float wv;
        if (r < 768) wv = W_feat[i];
        else if (r < 1024) wv = W_emb[i - 768 * 256];
        else wv = W_ih[i - 1024 * 256];
        g_Wcat[i] = wv;
    }
    if (i < 2048) {
        float b;
        if (i < 768) b = b_feat[i];
        else if (i < 1024) b = b_emb[i - 768];
        else b = b_ih[i - 1024] + b_hh[i - 1024];
        g_bcat[i] = b;
    }
    if (i < 65536) {
        int kk = i >> 8, k = i & 255;
        float4 v;
        v.x = W_hh[(0 + k) * 256 + kk];
        v.y = W_hh[(256 + k) * 256 + kk];
        v.z = W_hh[(512 + k) * 256 + kk];
        v.w = W_hh[(768 + k) * 256 + kk];
        g_Wpack[i] = v;
    }
    if (i < 16384) {
        int j = i >> 5, a = i & 31;
        g_Wp2T[i] = Wp2[a * 512 + j];
    }
}

// ---------------- h_pi/c_pi masked passthrough ----------------
__global__ void hpi_kernel(const float* __restrict__ starts, const float* __restrict__ h_pi,
                           const float* __restrict__ c_pi, float* __restrict__ out) {
    int s = blockIdx.x, tid = threadIdx.x;
    __shared__ float red[256];
    float p = 1.f;
    for (int t = tid; t < TSTEPS; t += 256) p *= (1.f - starts[s * TSTEPS + t]);
    red[tid] = p;
    __syncthreads();
    for (int st = 128; st; st >>= 1) {
        if (tid < st) red[tid] *= red[tid + st];
        __syncthreads();
    }
    float m = red[0];
    size_t base = (size_t)3 * NROWS;
    out[base + s * 256 + tid] = h_pi[s * 256 + tid] * m;
    out[base + 16384 + s * 256 + tid] = c_pi[s * 256 + tid] * m;
}

// ---------------- tiled fp32 GEMM (f32x2 inner), C = act(A @ W^T + bias) ----------------
// MODE 0: pre-GEMM -> routes cols [0,768)->C0(f1), [768,1024)->C1(opi), [1024,2048)->C2(xg, LSTM layout)
// MODE 1: head GEMM -> relu, C0[n*512+c]
#define BM 128
#define BN 64
#define BK 16

template <int MODE>
__global__ void __launch_bounds__(256) gemm_kernel(
    const float* __restrict__ A0, const float* __restrict__ A1,
    int K0, int Ktot, int lda0, int lda1,
    const float* __restrict__ W, int ldw,
    const float* __restrict__ bias,
    float* __restrict__ C0, float* __restrict__ C1, float* __restrict__ C2) {
    __shared__ __align__(16) float As[BK][BM];
    __shared__ __align__(16) float Bs[BK][BN];
    int tid = threadIdx.x;
    int colBase = blockIdx.x * BN;
    int rowBase = blockIdx.y * BM;
    int ty = tid >> 4, tx = tid & 15;
    int m0 = ty * 8, c0 = tx * 4;

    unsigned long long acc[4][4];
#pragma unroll
    for (int i = 0; i < 4; i++)
#pragma unroll
        for (int j = 0; j < 4; j++) acc[i][j] = 0ULL;

    for (int kb = 0; kb < Ktot; kb += BK) {
        const float* Asrc;
        int lda, kloc;
        if (kb < K0) { Asrc = A0; lda = lda0; kloc = kb; }
        else { Asrc = A1; lda = lda1; kloc = kb - K0; }
#pragma unroll
        for (int r = 0; r < 2; r++) {
            int p = tid + r * 256;
            int row = p >> 2, k4 = (p & 3) * 4;
            float4 v = *(const float4*)&Asrc[(size_t)(rowBase + row) * lda + kloc + k4];
            As[k4 + 0][row] = v.x;
            As[k4 + 1][row] = v.y;
            As[k4 + 2][row] = v.z;
            As[k4 + 3][row] = v.w;
        }
        {
            int p = tid;
            int col = p >> 2, k4 = (p & 3) * 4;
            float4 v = *(const float4*)&W[(size_t)(colBase + col) * ldw + kb + k4];
            Bs[k4 + 0][col] = v.x;
            Bs[k4 + 1][col] = v.y;
            Bs[k4 + 2][col] = v.z;
            Bs[k4 + 3][col] = v.w;
        }
        __syncthreads();
#pragma unroll
        for (int kk = 0; kk < BK; kk++) {
            unsigned long long a2[4];
#pragma unroll
            for (int i = 0; i < 4; i++) a2[i] = *(const unsigned long long*)&As[kk][m0 + 2 * i];
#pragma unroll
            for (int j = 0; j < 4; j++) {
                float b = Bs[kk][c0 + j];
                unsigned long long bb = pack2(b, b);
#pragma unroll
                for (int i = 0; i < 4; i++) acc[i][j] = ffma2(a2[i], bb, acc[i][j]);
            }
        }
        __syncthreads();
    }
#pragma unroll
    for (int j = 0; j < 4; j++) {
        int c = colBase + c0 + j;
        float bv = bias[c];
#pragma unroll
        for (int i = 0; i < 4; i++) {
            float v0, v1;
            unpack2(acc[i][j], v0, v1);
            v0 += bv;
            v1 += bv;
            int r0 = rowBase + m0 + 2 * i;
#pragma unroll
            for (int q = 0; q < 2; q++) {
                int n = r0 + q;
                float v = q ? v1 : v0;
                if (MODE == 0) {
                    if (c < 768) C0[(size_t)n * 768 + c] = v;
                    else if (c < 1024) C1[(size_t)n * 256 + (c - 768)] = v;
                    else {
                        int s = n >> 11, t = n & 2047;
                        C2[((size_t)((t << 6) | s) << 10) + (c - 1024)] = v;
                    }
                } else {
                    C0[((size_t)n << 9) + c] = fmaxf(v, 0.f);
                }
            }
        }
    }
}

// ---------------- LSTM scan: one CTA per sequence ----------------
__global__ void __launch_bounds__(256) lstm_kernel(
    const float* __restrict__ starts, const float* __restrict__ h0,
    const float* __restrict__ c0v, const float4* __restrict__ Wpack,
    const float* __restrict__ xg, float* __restrict__ hs,
    float* __restrict__ out) {
    int s = blockIdx.x, k = threadIdx.x;
    __shared__ __align__(16) float2 hbuf[2][256];
    float c = c0v[s * 256 + k];
    float h = h0[s * 256 + k];
    hbuf[0][k] = make_float2(h, h);
    __syncthreads();
    const ulonglong2* __restrict__ Wp = (const ulonglong2*)Wpack;
    int cur = 0;
    float hn = h;
    for (int t = 0; t < TSTEPS; t++) {
        float m = 1.0f - starts[s * TSTEPS + t];
        const float* xgp = xg + ((size_t)(t * 64 + s) << 10);
        unsigned long long aif = 0ULL, ago = 0ULL;
        const unsigned long long* hb = (const unsigned long long*)hbuf[cur];
#pragma unroll 8
        for (int kk = 0; kk < 256; kk++) {
            ulonglong2 w = Wp[(kk << 8) + k];
            unsigned long long hh = hb[kk];
            aif = ffma2(w.x, hh, aif);
            ago = ffma2(w.y, hh, ago);
        }
        float di, df, dg, dq;
        unpack2(aif, di, df);
        unpack2(ago, dg, dq);
        float gi = xgp[k] + m * di;
        float gf = xgp[256 + k] + m * df;
        float gg = xgp[512 + k] + m * dg;
        float go = xgp[768 + k] + m * dq;
        c *= m;
        float ii = 1.f / (1.f + expf(-gi));
        float ff = 1.f / (1.f + expf(-gf));
        float gt = tanhf(gg);
        float oo = 1.f / (1.f + expf(-go));
        c = ff * c + ii * gt;
        hn = oo * tanhf(c);
        hs[((size_t)s * TSTEPS + t) * 256 + k] = hn;
        hbuf[cur ^ 1][k] = make_float2(hn, hn);
        cur ^= 1;
        __syncthreads();
    }
    size_t base = (size_t)3 * NROWS;
    out[base + 32768 + s * 256 + k] = hn;
    out[base + 49152 + s * 256 + k] = c;
}

// ---------------- final: logits, argmax, log_prob, value ----------------
__global__ void __launch_bounds__(256) head_final(
    const float* __restrict__ HP, const float* __restrict__ HV,
    const float* __restrict__ bp2, const float* __restrict__ Wv2,
    const float* __restrict__ bv2, const float* __restrict__ Wp2T,
    float* __restrict__ out) {
    extern __shared__ float sm[];
    float* sW = sm;            // 16384
    float* sRow = sm + 16384;  // 8*512
    int tid = threadIdx.x, lane = tid & 31, w = tid >> 5;
    for (int i = tid; i < 16384; i += 256) sW[i] = Wp2T[i];
    __syncthreads();
    int n = blockIdx.x * 8 + w;

#pragma unroll
    for (int i = 0; i < 16; i++) sRow[w * 512 + i * 32 + lane] = HP[((size_t)n << 9) + i * 32 + lane];
    __syncwarp();

    float acc = bp2[lane];
    const float* r = &sRow[w * 512];
#pragma unroll 8
    for (int j = 0; j < 512; j++) acc = fmaf(sW[j * 32 + lane], r[j], acc);

    float vacc = 0.f;
#pragma unroll
    for (int i = 0; i < 16; i++) vacc = fmaf(Wv2[i * 32 + lane], HV[((size_t)n << 9) + i * 32 + lane], vacc);
#pragma unroll
    for (int o = 16; o; o >>= 1) vacc += __shfl_xor_sync(0xffffffffu, vacc, o);

    float l = acc;
    float mx = l;
#pragma unroll
    for (int o = 16; o; o >>= 1) mx = fmaxf(mx, __shfl_xor_sync(0xffffffffu, mx, o));
    int best = (l == mx) ? lane : 64;
#pragma unroll
    for (int o = 16; o; o >>= 1) best = min(best, __shfl_xor_sync(0xffffffffu, best, o));
    float e = expf(l - mx);
#pragma unroll
    for (int o = 16; o; o >>= 1) e += __shfl_xor_sync(0xffffffffu, e, o);

    if (lane == 0) {
        out[n] = (float)best;
        out[NROWS + n] = vacc + bv2[0];
        out[2 * NROWS + n] = -logf(e);
    }
}

// ---------------- launch ----------------
extern "C" void kernel_launch(void* const* d_in, const int* in_sizes, int n_in,
                              void* d_out, int out_size) {
    const float* features = (const float*)d_in[0];
    const float* episode_starts = (const float*)d_in[1];
    const float* h_pi = (const float*)d_in[2];
    const float* c_pi = (const float*)d_in[3];
    const float* h_vf = (const float*)d_in[4];
    const float* c_vf = (const float*)d_in[5];
    const float* W_feat = (const float*)d_in[6];
    const float* b_feat = (const float*)d_in[7];
    const float* W_emb = (const float*)d_in[8];
    const float* b_emb = (const float*)d_in[9];
    const float* W_ih = (const float*)d_in[10];
    const float* W_hh = (const float*)d_in[11];
    const float* b_ih = (const float*)d_in[12];
    const float* b_hh = (const float*)d_in[13];
    const float* Wp1 = (const float*)d_in[14];
    const float* bp1 = (const float*)d_in[15];
    const float* Wp2 = (const float*)d_in[16];
    const float* bp2 = (const float*)d_in[17];
    const float* Wv1 = (const float*)d_in[18];
    const float* bv1 = (const float*)d_in[19];
    const float* Wv2 = (const float*)d_in[20];
    const float* bv2 = (const float*)d_in[21];
    float* out = (float*)d_out;

    float *p_Wcat, *p_bcat, *p_Wp2T, *p_f1, *p_opi, *p_xg, *p_hs;
    float4* p_Wpack;
    cudaGetSymbolAddress((void**)&p_Wcat, g_Wcat);
    cudaGetSymbolAddress((void**)&p_bcat, g_bcat);
    cudaGetSymbolAddress((void**)&p_Wpack, g_Wpack);
    cudaGetSymbolAddress((void**)&p_Wp2T, g_Wp2T);
    cudaGetSymbolAddress((void**)&p_f1, g_f1);
    cudaGetSymbolAddress((void**)&p_opi, g_opi);
    cudaGetSymbolAddress((void**)&p_xg, g_xg);
    cudaGetSymbolAddress((void**)&p_hs, g_hs);
    float* p_HP = p_xg;                       // reuse xg scratch after LSTM consumed it
    float* p_HV = p_xg + (size_t)NROWS * 512;

    prep_kernel<<<2048, 256>>>(W_feat, b_feat, W_emb, b_emb, W_ih, W_hh, b_ih, b_hh, Wp2);
    hpi_kernel<<<NSEQ, 256>>>(episode_starts, h_pi, c_pi, out);

    // pre-GEMM: features(N,256) @ Wcat(2048,256)^T -> f1 / opi / xg
    gemm_kernel<0><<<dim3(2048 / BN, NROWS / BM), 256>>>(
        features, features, 256, 256, 256, 256, p_Wcat, 256, p_bcat, p_f1, p_opi, p_xg);

    lstm_kernel<<<NSEQ, 256>>>(episode_starts, h_vf, c_vf, p_Wpack, p_xg, p_hs, out);

    // heads: latent(1024 = f1[768] ++ other[256]) -> relu(512)
    gemm_kernel<1><<<dim3(512 / BN, NROWS / BM), 256>>>(
        p_f1, p_opi, 768, 1024, 768, 256, Wp1, 1024, bp1, p_HP, nullptr, nullptr);
    gemm_kernel<1><<<dim3(512 / BN, NROWS / BM), 256>>>(
        p_f1, p_hs, 768, 1024, 768, 256, Wv1, 1024, bv1, p_HV, nullptr, nullptr);

    cudaFuncSetAttribute(head_final, cudaFuncAttributeMaxDynamicSharedMemorySize, 81920);
    head_final<<<NROWS / 8, 256, 81920>>>(p_HP, p_HV, bp2, Wv2, bv2, p_Wp2T, out);
}

// round 2
// speedup vs baseline: 1.7469x; 1.7469x over previous
#include <cuda_runtime.h>
#include <cuda_bf16.h>
#include <cstdint>
#include <cstddef>

#define NROWS 131072
#define NSEQ 64
#define TSTEPS 2048

// ---------------- scratch ----------------
__device__ __align__(16) float g_Wcat[2048 * 256];
__device__ float g_bcat[2048];
__device__ __align__(16) uint4 g_WpackH[128 * 256];   // [kk2][k]: {bf16x2(i,f)|kk even, (g,o)|kk even, (i,f)|kk odd, (g,o)|kk odd}
__device__ float g_Wp2T[512 * 32];
__device__ __align__(16) float g_f1[(size_t)NROWS * 768];
__device__ __align__(16) float g_opi[(size_t)NROWS * 256];
__device__ __align__(16) float g_xg[(size_t)NROWS * 1024];   // reused as HP/HV after LSTM
__device__ __align__(16) float g_hs[(size_t)NROWS * 256];

// ---------------- f32x2 helpers ----------------
__device__ __forceinline__ unsigned long long ffma2(unsigned long long a, unsigned long long b, unsigned long long c) {
    asm("fma.rn.f32x2 %0, %1, %2, %3;" : "=l"(c) : "l"(a), "l"(b), "l"(c));
    return c;
}
__device__ __forceinline__ unsigned long long pack2(float lo, float hi) {
    unsigned long long r;
    asm("mov.b64 %0, {%1, %2};" : "=l"(r) : "f"(lo), "f"(hi));
    return r;
}
__device__ __forceinline__ void unpack2(unsigned long long v, float& a, float& b) {
    asm("mov.b64 {%0, %1}, %2;" : "=f"(a), "=f"(b) : "l"(v));
}
__device__ __forceinline__ unsigned long long pack2b(unsigned lo, unsigned hi) {
    unsigned long long r;
    asm("mov.b64 %0, {%1, %2};" : "=l"(r) : "r"(lo), "r"(hi));
    return r;
}
// bf16x2 (lo=elem0, hi=elem1) -> f32x2
__device__ __forceinline__ unsigned long long bfexp(unsigned r) {
    return pack2b(r << 16, r & 0xffff0000u);
}
__device__ __forceinline__ float sigf(float x) { return __fdividef(1.f, 1.f + __expf(-x)); }
__device__ __forceinline__ float tanha(float x) {
    float y;
    asm("tanh.approx.f32 %0, %1;" : "=f"(y) : "f"(x));
    return y;
}

// ---------------- prep ----------------
__global__ void prep_kernel(const float* __restrict__ W_feat, const float* __restrict__ b_feat,
                            const float* __restrict__ W_emb, const float* __restrict__ b_emb,
                            const float* __restrict__ W_ih, const float* __restrict__ W_hh,
                            const float* __restrict__ b_ih, const float* __restrict__ b_hh,
                            const float* __restrict__ Wp2) {
    int i = blockIdx.x * 256 + threadIdx.x;   // up to 524288
    {
        int r = i >> 8;
        float wv;
        if (r < 768) wv = W_feat[i];
        else if (r < 1024) wv = W_emb[i - 768 * 256];
        else wv = W_ih[i - 1024 * 256];
        g_Wcat[i] = wv;
    }
    if (i < 2048) {
        float b;
        if (i < 768) b = b_feat[i];
        else if (i < 1024) b = b_emb[i - 768];
        else b = b_ih[i - 1024] + b_hh[i - 1024];
        g_bcat[i] = b;
    }
    if (i < 65536) {
        int kk = i >> 8, k = i & 255;
        float wi = W_hh[(0 + k) * 256 + kk];
        float wf = W_hh[(256 + k) * 256 + kk];
        float wg = W_hh[(512 + k) * 256 + kk];
        float wo = W_hh[(768 + k) * 256 + kk];
        __nv_bfloat162 bif = __floats2bfloat162_rn(wi, wf);
        __nv_bfloat162 bgo = __floats2bfloat162_rn(wg, wo);
        unsigned uif = *(unsigned*)&bif;
        unsigned ugo = *(unsigned*)&bgo;
        int kk2 = kk >> 1, half = kk & 1;
        ((uint2*)g_WpackH)[(kk2 << 9) + (k << 1) + half] = make_uint2(uif, ugo);
    }
    if (i < 16384) {
        int j = i >> 5, a = i & 31;
        g_Wp2T[i] = Wp2[a * 512 + j];
    }
}

// ---------------- h_pi/c_pi masked passthrough ----------------
__global__ void hpi_kernel(const float* __restrict__ starts, const float* __restrict__ h_pi,
                           const float* __restrict__ c_pi, float* __restrict__ out) {
    int s = blockIdx.x, tid = threadIdx.x;
    __shared__ float red[256];
    float p = 1.f;
    for (int t = tid; t < TSTEPS; t += 256) p *= (1.f - starts[s * TSTEPS + t]);
    red[tid] = p;
    __syncthreads();
    for (int st = 128; st; st >>= 1) {
        if (tid < st) red[tid] *= red[tid + st];
        __syncthreads();
    }
    float m = red[0];
    size_t base = (size_t)3 * NROWS;
    out[base + s * 256 + tid] = h_pi[s * 256 + tid] * m;
    out[base + 16384 + s * 256 + tid] = c_pi[s * 256 + tid] * m;
}

// ---------------- GEMM: 128x128x16 tiles, 8x8 per thread, f32x2 ----------------
#define BM 128
#define BN 128
#define BK 16
#define APAD 132

template <int MODE>
__global__ void __launch_bounds__(256) gemm_kernel(
    const float* __restrict__ A0, const float* __restrict__ A1,
    int K0, int Ktot, int lda0, int lda1,
    const float* __restrict__ W, int ldw,
    const float* __restrict__ bias,
    float* __restrict__ C0, float* __restrict__ C1, float* __restrict__ C2) {
    __shared__ __align__(16) float As[BK][APAD];
    __shared__ __align__(16) float Bs[BK][APAD];
    int tid = threadIdx.x;
    int colBase = blockIdx.x * BN;
    int rowBase = blockIdx.y * BM;
    int tx = tid & 15, ty = tid >> 4;
    int m0 = ty * 8, c0 = tx * 8;

    int p0 = tid, p1 = tid + 256;
    int lr0 = p0 >> 2, lk0 = (p0 & 3) * 4;
    int lr1 = p1 >> 2, lk1 = (p1 & 3) * 4;

    unsigned long long acc[4][8];
#pragma unroll
    for (int i = 0; i < 4; i++)
#pragma unroll
        for (int j = 0; j < 8; j++) acc[i][j] = 0ULL;

    float4 ra0, ra1, rb0, rb1;
    // initial load
    {
        const float* Asrc = (0 < K0) ? A0 : A1;
        int lda = (0 < K0) ? lda0 : lda1;
        ra0 = *(const float4*)&Asrc[(size_t)(rowBase + lr0) * lda + lk0];
        ra1 = *(const float4*)&Asrc[(size_t)(rowBase + lr1) * lda + lk1];
        rb0 = *(const float4*)&W[(size_t)(colBase + lr0) * ldw + lk0];
        rb1 = *(const float4*)&W[(size_t)(colBase + lr1) * ldw + lk1];
    }
    // initial store
    As[lk0 + 0][lr0] = ra0.x; As[lk0 + 1][lr0] = ra0.y; As[lk0 + 2][lr0] = ra0.z; As[lk0 + 3][lr0] = ra0.w;
    As[lk1 + 0][lr1] = ra1.x; As[lk1 + 1][lr1] = ra1.y; As[lk1 + 2][lr1] = ra1.z; As[lk1 + 3][lr1] = ra1.w;
    Bs[lk0 + 0][lr0] = rb0.x; Bs[lk0 + 1][lr0] = rb0.y; Bs[lk0 + 2][lr0] = rb0.z; Bs[lk0 + 3][lr0] = rb0.w;
    Bs[lk1 + 0][lr1] = rb1.x; Bs[lk1 + 1][lr1] = rb1.y; Bs[lk1 + 2][lr1] = rb1.z; Bs[lk1 + 3][lr1] = rb1.w;
    __syncthreads();

    for (int kb = 0; kb < Ktot; kb += BK) {
        bool notlast = (kb + BK < Ktot);
        if (notlast) {
            int kn = kb + BK;
            const float* Asrc;
            int lda, kloc;
            if (kn < K0) { Asrc = A0; lda = lda0; kloc = kn; }
            else { Asrc = A1; lda = lda1; kloc = kn - K0; }
            ra0 = *(const float4*)&Asrc[(size_t)(rowBase + lr0) * lda + kloc + lk0];
            ra1 = *(const float4*)&Asrc[(size_t)(rowBase + lr1) * lda + kloc + lk1];
            rb0 = *(const float4*)&W[(size_t)(colBase + lr0) * ldw + kn + lk0];
            rb1 = *(const float4*)&W[(size_t)(colBase + lr1) * ldw + kn + lk1];
        }
#pragma unroll
        for (int kk = 0; kk < BK; kk++) {
            unsigned long long a2[4];
#pragma unroll
            for (int i = 0; i < 4; i++) a2[i] = *(const unsigned long long*)&As[kk][m0 + 2 * i];
            float4 b0 = *(const float4*)&Bs[kk][c0];
            float4 b1 = *(const float4*)&Bs[kk][c0 + 4];
            float bs[8] = {b0.x, b0.y, b0.z, b0.w, b1.x, b1.y, b1.z, b1.w};
#pragma unroll
            for (int j = 0; j < 8; j++) {
                unsigned long long bb = pack2(bs[j], bs[j]);
#pragma unroll
                for (int i = 0; i < 4; i++) acc[i][j] = ffma2(a2[i], bb, acc[i][j]);
            }
        }
        __syncthreads();
        if (notlast) {
            As[lk0 + 0][lr0] = ra0.x; As[lk0 + 1][lr0] = ra0.y; As[lk0 + 2][lr0] = ra0.z; As[lk0 + 3][lr0] = ra0.w;
            As[lk1 + 0][lr1] = ra1.x; As[lk1 + 1][lr1] = ra1.y; As[lk1 + 2][lr1] = ra1.z; As[lk1 + 3][lr1] = ra1.w;
            Bs[lk0 + 0][lr0] = rb0.x; Bs[lk0 + 1][lr0] = rb0.y; Bs[lk0 + 2][lr0] = rb0.z; Bs[lk0 + 3][lr0] = rb0.w;
            Bs[lk1 + 0][lr1] = rb1.x; Bs[lk1 + 1][lr1] = rb1.y; Bs[lk1 + 2][lr1] = rb1.z; Bs[lk1 + 3][lr1] = rb1.w;
            __syncthreads();
        }
    }

    // bias
    float bv[8];
    {
        float4 q0 = *(const float4*)&bias[colBase + c0];
        float4 q1 = *(const float4*)&bias[colBase + c0 + 4];
        bv[0] = q0.x; bv[1] = q0.y; bv[2] = q0.z; bv[3] = q0.w;
        bv[4] = q1.x; bv[5] = q1.y; bv[6] = q1.z; bv[7] = q1.w;
    }
#pragma unroll
    for (int i = 0; i < 4; i++) {
        float vlo[8], vhi[8];
#pragma unroll
        for (int j = 0; j < 8; j++) {
            unpack2(acc[i][j], vlo[j], vhi[j]);
            vlo[j] += bv[j];
            vhi[j] += bv[j];
        }
        int r0 = rowBase + m0 + 2 * i;
#pragma unroll
        for (int q = 0; q < 2; q++) {
            int n = r0 + q;
            float* src = q ? vhi : vlo;
            float* dst;
            if (MODE == 1) {
#pragma unroll
                for (int j = 0; j < 8; j++) src[j] = fmaxf(src[j], 0.f);
                dst = &C0[((size_t)n << 9) + colBase + c0];
            } else {
                if (colBase < 768) dst = &C0[(size_t)n * 768 + colBase + c0];
                else if (colBase < 1024) dst = &C1[(size_t)n * 256 + (colBase - 768) + c0];
                else {
                    int s = n >> 11, t = n & 2047;
                    dst = &C2[((size_t)((t << 6) | s) << 10) + (colBase - 1024) + c0];
                }
            }
            float4 o0 = make_float4(src[0], src[1], src[2], src[3]);
            float4 o1 = make_float4(src[4], src[5], src[6], src[7]);
            *(float4*)&dst[0] = o0;
            *(float4*)&dst[4] = o1;
        }
    }
}

// ---------------- LSTM scan: one CTA per sequence, bf16 W ----------------
__global__ void __launch_bounds__(256) lstm_kernel(
    const float* __restrict__ starts, const float* __restrict__ h0,
    const float* __restrict__ c0v, const uint4* __restrict__ WpH,
    const float* __restrict__ xg, float* __restrict__ hs,
    float* __restrict__ out) {
    int s = blockIdx.x, k = threadIdx.x;
    __shared__ __align__(16) float2 hbuf[2][256];
    float c = c0v[s * 256 + k];
    float h = h0[s * 256 + k];
    hbuf[0][k] = make_float2(h, h);
    __syncthreads();
    int cur = 0;
    float hn = h;
    for (int t = 0; t < TSTEPS; t++) {
        float m = 1.0f - starts[s * TSTEPS + t];
        const float* xgp = xg + ((size_t)(t * 64 + s) << 10);
        unsigned long long aif = 0ULL, ago = 0ULL;
        const ulonglong2* hb2 = (const ulonglong2*)hbuf[cur];
#pragma unroll 8
        for (int kk2 = 0; kk2 < 128; kk2++) {
            uint4 w = WpH[(kk2 << 8) + k];
            ulonglong2 hh = hb2[kk2];
            aif = ffma2(bfexp(w.x), hh.x, aif);
            ago = ffma2(bfexp(w.y), hh.x, ago);
            aif = ffma2(bfexp(w.z), hh.y, aif);
            ago = ffma2(bfexp(w.w), hh.y, ago);
        }
        float di, df, dg, dq;
        unpack2(aif, di, df);
        unpack2(ago, dg, dq);
        float gi = xgp[k] + m * di;
        float gf = xgp[256 + k] + m * df;
        float gg = xgp[512 + k] + m * dg;
        float go = xgp[768 + k] + m * dq;
        c *= m;
        c = sigf(gf) * c + sigf(gi) * tanha(gg);
        hn = sigf(go) * tanha(c);
        hs[((size_t)s * TSTEPS + t) * 256 + k] = hn;
        hbuf[cur ^ 1][k] = make_float2(hn, hn);
        cur ^= 1;
        __syncthreads();
    }
    size_t base = (size_t)3 * NROWS;
    out[base + 32768 + s * 256 + k] = hn;
    out[base + 49152 + s * 256 + k] = c;
}

// ---------------- final: logits, argmax, log_prob, value ----------------
__global__ void __launch_bounds__(256) head_final(
    const float* __restrict__ HP, const float* __restrict__ HV,
    const float* __restrict__ bp2, const float* __restrict__ Wv2,
    const float* __restrict__ bv2, const float* __restrict__ Wp2T,
    float* __restrict__ out) {
    extern __shared__ float sm[];
    float* sW = sm;            // 16384
    float* sRow = sm + 16384;  // 8*512
    int tid = threadIdx.x, lane = tid & 31, w = tid >> 5;
    for (int i = tid; i < 16384; i += 256) sW[i] = Wp2T[i];
    __syncthreads();
    int n = blockIdx.x * 8 + w;

#pragma unroll
    for (int i = 0; i < 16; i++) sRow[w * 512 + i * 32 + lane] = HP[((size_t)n << 9) + i * 32 + lane];
    __syncwarp();

    float acc = bp2[lane];
    const float* r = &sRow[w * 512];
#pragma unroll 8
    for (int j = 0; j < 512; j++) acc = fmaf(sW[j * 32 + lane], r[j], acc);

    float vacc = 0.f;
#pragma unroll
    for (int i = 0; i < 16; i++) vacc = fmaf(Wv2[i * 32 + lane], HV[((size_t)n << 9) + i * 32 + lane], vacc);
#pragma unroll
    for (int o = 16; o; o >>= 1) vacc += __shfl_xor_sync(0xffffffffu, vacc, o);

    float l = acc;
    float mx = l;
#pragma unroll
    for (int o = 16; o; o >>= 1) mx = fmaxf(mx, __shfl_xor_sync(0xffffffffu, mx, o));
    int best = (l == mx) ? lane : 64;
#pragma unroll
    for (int o = 16; o; o >>= 1) best = min(best, __shfl_xor_sync(0xffffffffu, best, o));
    float e = expf(l - mx);
#pragma unroll
    for (int o = 16; o; o >>= 1) e += __shfl_xor_sync(0xffffffffu, e, o);

    if (lane == 0) {
        out[n] = (float)best;
        out[NROWS + n] = vacc + bv2[0];
        out[2 * NROWS + n] = -logf(e);
    }
}

// ---------------- launch ----------------
extern "C" void kernel_launch(void* const* d_in, const int* in_sizes, int n_in,
                              void* d_out, int out_size) {
    const float* features = (const float*)d_in[0];
    const float* episode_starts = (const float*)d_in[1];
    const float* h_pi = (const float*)d_in[2];
    const float* c_pi = (const float*)d_in[3];
    const float* h_vf = (const float*)d_in[4];
    const float* c_vf = (const float*)d_in[5];
    const float* W_feat = (const float*)d_in[6];
    const float* b_feat = (const float*)d_in[7];
    const float* W_emb = (const float*)d_in[8];
    const float* b_emb = (const float*)d_in[9];
    const float* W_ih = (const float*)d_in[10];
    const float* W_hh = (const float*)d_in[11];
    const float* b_ih = (const float*)d_in[12];
    const float* b_hh = (const float*)d_in[13];
    const float* Wp1 = (const float*)d_in[14];
    const float* bp1 = (const float*)d_in[15];
    const float* Wp2 = (const float*)d_in[16];
    const float* bp2 = (const float*)d_in[17];
    const float* Wv1 = (const float*)d_in[18];
    const float* bv1 = (const float*)d_in[19];
    const float* Wv2 = (const float*)d_in[20];
    const float* bv2 = (const float*)d_in[21];
    float* out = (float*)d_out;

    float *p_Wcat, *p_bcat, *p_Wp2T, *p_f1, *p_opi, *p_xg, *p_hs;
    uint4* p_WpH;
    cudaGetSymbolAddress((void**)&p_Wcat, g_Wcat);
    cudaGetSymbolAddress((void**)&p_bcat, g_bcat);
    cudaGetSymbolAddress((void**)&p_WpH, g_WpackH);
    cudaGetSymbolAddress((void**)&p_Wp2T, g_Wp2T);
    cudaGetSymbolAddress((void**)&p_f1, g_f1);
    cudaGetSymbolAddress((void**)&p_opi, g_opi);
    cudaGetSymbolAddress((void**)&p_xg, g_xg);
    cudaGetSymbolAddress((void**)&p_hs, g_hs);
    float* p_HP = p_xg;
    float* p_HV = p_xg + (size_t)NROWS * 512;

    prep_kernel<<<2048, 256>>>(W_feat, b_feat, W_emb, b_emb, W_ih, W_hh, b_ih, b_hh, Wp2);
    hpi_kernel<<<NSEQ, 256>>>(episode_starts, h_pi, c_pi, out);

    // pre-GEMM: features(N,256) @ Wcat(2048,256)^T -> f1 / opi / xg
    gemm_kernel<0><<<dim3(2048 / BN, NROWS / BM), 256>>>(
        features, features, 256, 256, 256, 256, p_Wcat, 256, p_bcat, p_f1, p_opi, p_xg);

    lstm_kernel<<<NSEQ, 256>>>(episode_starts, h_vf, c_vf, p_WpH, p_xg, p_hs, out);

    // heads: latent(1024 = f1[768] ++ other[256]) -> relu(512)
    gemm_kernel<1><<<dim3(512 / BN, NROWS / BM), 256>>>(
        p_f1, p_opi, 768, 1024, 768, 256, Wp1, 1024, bp1, p_HP, nullptr, nullptr);
    gemm_kernel<1><<<dim3(512 / BN, NROWS / BM), 256>>>(
        p_f1, p_hs, 768, 1024, 768, 256, Wv1, 1024, bv1, p_HV, nullptr, nullptr);

    cudaFuncSetAttribute(head_final, cudaFuncAttributeMaxDynamicSharedMemorySize, 81920);
    head_final<<<NROWS / 8, 256, 81920>>>(p_HP, p_HV, bp2, Wv2, bv2, p_Wp2T, out);
}